// round 16
// baseline (speedup 1.0000x reference)
#include <cuda_runtime.h>
#include <stdint.h>
#include <math.h>

#define NEGV  -1e30f
#define SWT   256         // sw threads: 2 cols x 2 rows per thread-step
#define STEPS 511         // 256 + 255
#define FU    512         // feed u-rows
#define LOG2E 1.4426950408889634f
#define LN2   0.6931471805599453f

// ---- static device scratch ----
__device__ float  g_S[4 * 512 * 512];          // plain score matrices
__device__ float  g_n2[2 * 4 * 512];           // row norms
__device__ float4 g_Sf4[4 * FU * 256];         // skewed S feed (base-2 scaled)
__device__ float4 g_gof4[FU * 256];            // skewed go feed (scaled)
__device__ float4 g_gef4[FU * 256];            // skewed ge feed (scaled)
__device__ float4 g_Df4[4 * FU * 256];         // skewed D output (base-2 domain)
__device__ float  g_pm[256], g_ps[256];        // LSE partials (64 per batch)

__device__ __forceinline__ float ex2a(float x) {
    float r; asm("ex2.approx.ftz.f32 %0, %1;" : "=f"(r) : "f"(x)); return r;
}
__device__ __forceinline__ float lg2a(float x) {
    float r; asm("lg2.approx.ftz.f32 %0, %1;" : "=f"(r) : "f"(x)); return r;
}
__device__ __forceinline__ float lse2b(float a, float b) {
    float m = fmaxf(a, b), n = fminf(a, b);
    return m + lg2a(1.0f + ex2a(n - m));
}
__device__ __forceinline__ float lse3b(float a, float b) {   // LSE(a,b,0)
    float m = fmaxf(fmaxf(a, b), 0.f);
    return m + lg2a(ex2a(a - m) + ex2a(b - m) + ex2a(-m));
}

// ================= norms =================
__global__ void norm_kernel(const float* __restrict__ x, const float* __restrict__ y) {
    int w = (blockIdx.x * blockDim.x + threadIdx.x) >> 5;
    int lane = threadIdx.x & 31;
    #pragma unroll
    for (int s = 0; s < 16; s++) {
        int row = w + s * 256;
        const float* p = (row < 2048) ? (x + row * 128) : (y + (row - 2048) * 128);
        float v0 = p[lane], v1 = p[lane + 32], v2 = p[lane + 64], v3 = p[lane + 96];
        float sum = v0 * v0 + v1 * v1 + v2 * v2 + v3 * v3;
        #pragma unroll
        for (int o = 16; o > 0; o >>= 1) sum += __shfl_xor_sync(0xffffffffu, sum, o);
        if (lane == 0) g_n2[row] = sum;
    }
}

// ================= S = x2 + y2 - 2 x.y  (64x64 tiles) =================
__global__ void __launch_bounds__(256) dist_kernel(const float* __restrict__ x,
                                                   const float* __restrict__ y) {
    int b = blockIdx.z;
    int i0 = blockIdx.y * 64, j0 = blockIdx.x * 64;
    const float* xb = x + (b * 512 + i0) * 128;
    const float* yb = y + (b * 512 + j0) * 128;
    __shared__ float xs[16][64];
    __shared__ float ys[16][64];
    int tid = threadIdx.x;
    int tx = tid & 15, ty = tid >> 4;
    float acc[4][4];
    #pragma unroll
    for (int r = 0; r < 4; r++)
        #pragma unroll
        for (int c = 0; c < 4; c++) acc[r][c] = 0.f;

    for (int kc = 0; kc < 128; kc += 16) {
        __syncthreads();
        #pragma unroll
        for (int l = 0; l < 4; l++) {
            int e = tid + l * 256;
            int r = e >> 4, kk = e & 15;
            xs[kk][r] = xb[r * 128 + kc + kk];
            ys[kk][r] = yb[r * 128 + kc + kk];
        }
        __syncthreads();
        #pragma unroll
        for (int kk = 0; kk < 16; kk++) {
            float4 a  = *(const float4*)&xs[kk][ty * 4];
            float4 bv = *(const float4*)&ys[kk][tx * 4];
            float ar[4] = {a.x, a.y, a.z, a.w};
            float br[4] = {bv.x, bv.y, bv.z, bv.w};
            #pragma unroll
            for (int r = 0; r < 4; r++)
                #pragma unroll
                for (int c = 0; c < 4; c++)
                    acc[r][c] = fmaf(ar[r], br[c], acc[r][c]);
        }
    }
    float x2[4], y2[4];
    #pragma unroll
    for (int r = 0; r < 4; r++) x2[r] = g_n2[b * 512 + i0 + ty * 4 + r];
    #pragma unroll
    for (int c = 0; c < 4; c++) y2[c] = g_n2[2048 + b * 512 + j0 + tx * 4 + c];
    float* Sb = g_S + b * 262144;
    #pragma unroll
    for (int r = 0; r < 4; r++) {
        float4 o;
        o.x = x2[r] + y2[0] - 2.f * acc[r][0];
        o.y = x2[r] + y2[1] - 2.f * acc[r][1];
        o.z = x2[r] + y2[2] - 2.f * acc[r][2];
        o.w = x2[r] + y2[3] - 2.f * acc[r][3];
        *(float4*)&Sb[(i0 + ty * 4 + r) * 512 + j0 + tx * 4] = o;
    }
}

// ================= reskew: M[512][512] -> F4[u][t][q], base-2 scaled ============
// F[u][t][q] = LOG2E * M[2(u-t) + (q>>1)][2t + (q&1)]  if 0 <= u-t < 256, else 0
__global__ void __launch_bounds__(256) reskew_kernel(const float* __restrict__ go,
                                                     const float* __restrict__ ge) {
    int m = blockIdx.y;                 // 0..3 = S batches, 4 = go, 5 = ge
    int ut = blockIdx.x >> 3;           // 16 u-tiles of 32
    int jt = blockIdx.x & 7;            // 8 t-tiles of 32
    const float* src = (m < 4) ? (g_S + m * 262144) : ((m == 4) ? go : ge);
    float* dst = (m < 4) ? (float*)(g_Sf4 + m * (FU * 256)) :
                 ((m == 4) ? (float*)g_gof4 : (float*)g_gef4);
    int u0 = ut * 32, t0 = jt * 32;
    int rbase = 2 * (u0 - t0) - 62;     // 126 src rows
    int cbase = 2 * t0;                 // 64 src cols
    __shared__ float sm[126 * 65];
    int tid = threadIdx.x;
    #pragma unroll
    for (int l = 0; l < 32; l++) {
        int e = tid + l * 256;
        if (e < 126 * 64) {
            int rr = e >> 6, cc = e & 63;
            int gr = rbase + rr;
            sm[rr * 65 + cc] = (gr >= 0 && gr < 512) ?
                LOG2E * src[gr * 512 + cbase + cc] : 0.f;
        }
    }
    __syncthreads();
    #pragma unroll
    for (int l = 0; l < 16; l++) {
        int e = tid + l * 256;           // 4096 dst elements
        int q = e & 3, tr = (e >> 2) & 31, ur = e >> 7;
        int u = u0 + ur, t = t0 + tr;
        int dq = u - t;
        float v = 0.f;
        if (dq >= 0 && dq < 256) {
            int rr = 2 * (ur - tr) + (q >> 1) + 62;
            v = sm[rr * 65 + 2 * tr + (q & 1)];
        }
        dst[(u * 256 + t) * 4 + q] = v;
    }
}

// ================= wavefront soft-SW; windowed warp pipeline, no CTA barrier ====
__global__ __launch_bounds__(SWT, 1) void sw_kernel() {
    const int b = blockIdx.x;
    const int t = threadIdx.x, lane = t & 31, warp = t >> 5;
    const float4* S4  = g_Sf4 + b * (FU * 256);
    const float4* go4 = g_gof4;
    const float4* ge4 = g_gef4;
    float4* Df4 = g_Df4 + b * (FU * 256);

    // boundary ring: producer warp w (w<7) publishes its lane31 carries each step;
    // consumer warp w+1 lane0 reads slot (u-1). Windowed barriers keep the
    // producer >= 1 full 8-step window ahead, so reads always hit written slots.
    __shared__ volatile float ring[7][32][8];

    float hA = NEGV, IyA = NEGV, gA = 0.f;
    float hB = NEGV, IyB = NEGV;
    float BDlo = NEGV, BIlo = NEGV, Bglo = 0.f;
    float BDhi = NEGV, BIhi = NEGV, Bghi = 0.f;
    float gstale = 0.f;

    float4 sP = S4[t], goP = go4[t], geP = ge4[t];

    for (int u = 0; u < STEPS; u++) {
        if ((u & 7) == 0 && u > 0) {
            // entering window k = u/8
            if (warp > 0)               // consumer: wait for left to finish window k
                asm volatile("bar.sync %0, 64;" :: "r"(warp) : "memory");
            if (warp < 7 && u >= 16)    // producer: signal "finished window k-1"
                asm volatile("bar.sync %0, 64;" :: "r"(warp + 1) : "memory");
        }

        float4 sC = sP, goC = goP, geC = geP;
        {
            int idx = (u + 1) * 256 + t;
            sP = S4[idx]; goP = go4[idx]; geP = ge4[idx];
        }
        // neighbor fresh values (results of step u-1)
        float nDlo = __shfl_up_sync(0xffffffffu, BDlo, 1);
        float nIlo = __shfl_up_sync(0xffffffffu, BIlo, 1);
        float nglo = __shfl_up_sync(0xffffffffu, Bglo, 1);
        float nDhi = __shfl_up_sync(0xffffffffu, BDhi, 1);
        float nIhi = __shfl_up_sync(0xffffffffu, BIhi, 1);
        float nghi = __shfl_up_sync(0xffffffffu, Bghi, 1);
        if (lane == 0) {
            if (warp > 0) {
                int sl = (u - 1) & 31;
                nDlo = ring[warp - 1][sl][0];
                nIlo = ring[warp - 1][sl][1];
                nglo = ring[warp - 1][sl][2];
                nDhi = ring[warp - 1][sl][3];
                nIhi = ring[warp - 1][sl][4];
                nghi = ring[warp - 1][sl][5];
            } else {
                nDlo = NEGV; nIlo = NEGV; nglo = 0.f;
                nDhi = NEGV; nIhi = NEGV; nghi = 0.f;
            }
        }

        bool act = (u >= t) && (u - t < 256);
        if (act) {
            // rows ra = 2(u-t), rb = ra+1; cols ja = 2t, jb = 2t+1
            float ix1 = lse2b(nDlo - goC.x, nIlo - geC.x);
            float iy1 = lse2b(hA - goC.x, IyA - geC.x);
            float d1  = sC.x + gstale;
            float h1  = lse2b(d1, ix1);
            float g1  = lse3b(h1, iy1);

            float ix2 = lse2b(d1 - goC.y, ix1 - geC.y);
            float iy2 = lse2b(hB - goC.y, IyB - geC.y);
            float d2  = sC.y + gA;
            float h2  = lse2b(d2, ix2);
            float g2  = lse3b(h2, iy2);

            float ix3 = lse2b(nDhi - goC.z, nIhi - geC.z);
            float iy3 = lse2b(h1 - goC.z, iy1 - geC.z);
            float d3  = sC.z + nglo;
            float h3  = lse2b(d3, ix3);
            float g3  = lse3b(h3, iy3);

            float ix4 = lse2b(d3 - goC.w, ix3 - geC.w);
            float iy4 = lse2b(h2 - goC.w, iy2 - geC.w);
            float d4  = sC.w + g1;
            float h4  = lse2b(d4, ix4);
            float g4  = lse3b(h4, iy4);

            Df4[u * 256 + t] = make_float4(d1, d2, d3, d4);

            hA = h3; IyA = iy3; gA = g3;
            hB = h4; IyB = iy4;
            BDlo = d2; BIlo = ix2; Bglo = g2;
            BDhi = d4; BIhi = ix4; Bghi = g4;
        }
        gstale = nghi;
        if (lane == 31 && warp < 7) {     // publish current carries (every step)
            int sl = u & 31;
            ring[warp][sl][0] = BDlo; ring[warp][sl][1] = BIlo; ring[warp][sl][2] = Bglo;
            ring[warp][sl][3] = BDhi; ring[warp][sl][4] = BIhi; ring[warp][sl][5] = Bghi;
        }
    }
    // final producer arrival so consumer's last window-wait releases
    if (warp < 7)
        asm volatile("bar.sync %0, 64;" :: "r"(warp + 1) : "memory");
}

// ================= LSE over valid D slots (base-2 domain) =================
__global__ void lse_part() {
    int blk = blockIdx.x, b = blockIdx.y;    // 64 x 4
    const float4* Dv = g_Df4 + b * (FU * 256);
    int tid = threadIdx.x;
    float m = NEGV, s = 0.f;
    #pragma unroll
    for (int l = 0; l < 8; l++) {
        int slot = blk * 2048 + tid + l * 256;
        int u = slot >> 8, tc = slot & 255;
        int dq = u - tc;
        if (dq >= 0 && dq < 256) {
            float4 v = Dv[slot];
            float m4 = fmaxf(fmaxf(v.x, v.y), fmaxf(v.z, v.w));
            float nm = fmaxf(m, m4);
            s = s * ex2a(m - nm) + ex2a(v.x - nm) + ex2a(v.y - nm)
                                 + ex2a(v.z - nm) + ex2a(v.w - nm);
            m = nm;
        }
    }
    __shared__ float sm[256], ss[256];
    sm[tid] = m; ss[tid] = s;
    __syncthreads();
    for (int o = 128; o > 0; o >>= 1) {
        if (tid < o) {
            float m2 = sm[tid + o], s2 = ss[tid + o];
            float nm = fmaxf(sm[tid], m2);
            ss[tid] = ss[tid] * ex2a(sm[tid] - nm) + s2 * ex2a(m2 - nm);
            sm[tid] = nm;
        }
        __syncthreads();
    }
    if (tid == 0) { g_pm[b * 64 + blk] = sm[0]; g_ps[b * 64 + blk] = ss[0]; }
}

__global__ void lse_final(float* __restrict__ out) {
    int t = threadIdx.x;              // 256
    int b = t >> 6, r = t & 63;
    __shared__ float sm[256], ss[256], vv[4];
    sm[t] = g_pm[b * 64 + r]; ss[t] = g_ps[b * 64 + r];
    __syncthreads();
    for (int o = 32; o > 0; o >>= 1) {
        if (r < o) {
            float m2 = sm[t + o], s2 = ss[t + o];
            float nm = fmaxf(sm[t], m2);
            ss[t] = ss[t] * ex2a(sm[t] - nm) + s2 * ex2a(m2 - nm);
            sm[t] = nm;
        }
        __syncthreads();
    }
    if (r == 0) vv[b] = LN2 * (sm[t] + lg2a(ss[t]));
    __syncthreads();
    if (t == 0) out[0] = 0.25f * (vv[0] + vv[1] + vv[2] + vv[3]);
}

// ================= deskew: probas[r][j] = LN2 * Df4[t+(r>>1)][t=j>>1].q ==========
__global__ void __launch_bounds__(256) deskew_kernel(float* __restrict__ out) {
    int b = blockIdx.y;
    const float* Df = (const float*)(g_Df4 + b * (FU * 256));
    float* ob = out + 1 + b * 262144;
    int e0 = blockIdx.x * 256 + threadIdx.x;     // 128 blocks
    #pragma unroll
    for (int l = 0; l < 8; l++) {
        int e = e0 + l * 32768;
        int r = e >> 9, j = e & 511;
        int tc = j >> 1;
        int u = tc + (r >> 1);
        int q = ((r & 1) << 1) | (j & 1);
        ob[e] = LN2 * Df[(u * 256 + tc) * 4 + q];
    }
}

// ================= launcher =================
extern "C" void kernel_launch(void* const* d_in, const int* in_sizes, int n_in,
                              void* d_out, int out_size) {
    const float* x  = (const float*)d_in[0];
    const float* y  = (const float*)d_in[1];
    const float* go = (const float*)d_in[2];
    const float* ge = (const float*)d_in[3];
    float* out = (float*)d_out;

    norm_kernel<<<32, 256>>>(x, y);
    dist_kernel<<<dim3(8, 8, 4), 256>>>(x, y);
    reskew_kernel<<<dim3(128, 6), 256>>>(go, ge);
    sw_kernel<<<4, SWT>>>();
    lse_part<<<dim3(64, 4), 256>>>();
    deskew_kernel<<<dim3(128, 4), 256>>>(out);
    lse_final<<<1, 256>>>(out);
}

// round 17
// speedup vs baseline: 1.4951x; 1.4951x over previous
#include <cuda_runtime.h>
#include <stdint.h>
#include <math.h>

#define NEGV  -1e30f
#define SWT   256         // sw threads: 2 cols x 2 rows per thread-step
#define STEPS 511         // 256 + 255
#define FU    512         // feed u-rows
#define LOG2E 1.4426950408889634f
#define LN2   0.6931471805599453f

// ---- static device scratch ----
__device__ float  g_S[4 * 512 * 512];          // plain score matrices
__device__ float  g_n2[2 * 4 * 512];           // row norms
__device__ float4 g_Sf4[4 * FU * 256];         // skewed S feed (base-2 scaled)
__device__ float4 g_gof4[FU * 256];            // skewed go feed (scaled)
__device__ float4 g_gef4[FU * 256];            // skewed ge feed (scaled)
__device__ float4 g_Df4[4 * FU * 256];         // skewed D output (base-2 domain)
__device__ float  g_pm[512], g_ps[512];        // LSE partials (128 per batch)

__device__ __forceinline__ float ex2a(float x) {
    float r; asm("ex2.approx.ftz.f32 %0, %1;" : "=f"(r) : "f"(x)); return r;
}
__device__ __forceinline__ float lg2a(float x) {
    float r; asm("lg2.approx.ftz.f32 %0, %1;" : "=f"(r) : "f"(x)); return r;
}
// base-2 LSE of two base-2-domain values
__device__ __forceinline__ float lse2b(float a, float b) {
    float m = fmaxf(a, b), n = fminf(a, b);
    return m + lg2a(1.0f + ex2a(n - m));
}
// base-2 LSE of (a, b, 0)
__device__ __forceinline__ float lse3b(float a, float b) {
    float m = fmaxf(fmaxf(a, b), 0.f);
    return m + lg2a(ex2a(a - m) + ex2a(b - m) + ex2a(-m));
}

// ================= norms =================
__global__ void norm_kernel(const float* __restrict__ x, const float* __restrict__ y) {
    int w = (blockIdx.x * blockDim.x + threadIdx.x) >> 5;
    int lane = threadIdx.x & 31;
    #pragma unroll
    for (int s = 0; s < 16; s++) {
        int row = w + s * 256;
        const float* p = (row < 2048) ? (x + row * 128) : (y + (row - 2048) * 128);
        float v0 = p[lane], v1 = p[lane + 32], v2 = p[lane + 64], v3 = p[lane + 96];
        float sum = v0 * v0 + v1 * v1 + v2 * v2 + v3 * v3;
        #pragma unroll
        for (int o = 16; o > 0; o >>= 1) sum += __shfl_xor_sync(0xffffffffu, sum, o);
        if (lane == 0) g_n2[row] = sum;
    }
}

// ================= S = x2 + y2 - 2 x.y  (64x64 tiles) =================
__global__ void __launch_bounds__(256) dist_kernel(const float* __restrict__ x,
                                                   const float* __restrict__ y) {
    int b = blockIdx.z;
    int i0 = blockIdx.y * 64, j0 = blockIdx.x * 64;
    const float* xb = x + (b * 512 + i0) * 128;
    const float* yb = y + (b * 512 + j0) * 128;
    __shared__ float xs[16][64];
    __shared__ float ys[16][64];
    int tid = threadIdx.x;
    int tx = tid & 15, ty = tid >> 4;
    float acc[4][4];
    #pragma unroll
    for (int r = 0; r < 4; r++)
        #pragma unroll
        for (int c = 0; c < 4; c++) acc[r][c] = 0.f;

    for (int kc = 0; kc < 128; kc += 16) {
        __syncthreads();
        #pragma unroll
        for (int l = 0; l < 4; l++) {
            int e = tid + l * 256;
            int r = e >> 4, kk = e & 15;
            xs[kk][r] = xb[r * 128 + kc + kk];
            ys[kk][r] = yb[r * 128 + kc + kk];
        }
        __syncthreads();
        #pragma unroll
        for (int kk = 0; kk < 16; kk++) {
            float4 a  = *(const float4*)&xs[kk][ty * 4];
            float4 bv = *(const float4*)&ys[kk][tx * 4];
            float ar[4] = {a.x, a.y, a.z, a.w};
            float br[4] = {bv.x, bv.y, bv.z, bv.w};
            #pragma unroll
            for (int r = 0; r < 4; r++)
                #pragma unroll
                for (int c = 0; c < 4; c++)
                    acc[r][c] = fmaf(ar[r], br[c], acc[r][c]);
        }
    }
    float x2[4], y2[4];
    #pragma unroll
    for (int r = 0; r < 4; r++) x2[r] = g_n2[b * 512 + i0 + ty * 4 + r];
    #pragma unroll
    for (int c = 0; c < 4; c++) y2[c] = g_n2[2048 + b * 512 + j0 + tx * 4 + c];
    float* Sb = g_S + b * 262144;
    #pragma unroll
    for (int r = 0; r < 4; r++) {
        float4 o;
        o.x = x2[r] + y2[0] - 2.f * acc[r][0];
        o.y = x2[r] + y2[1] - 2.f * acc[r][1];
        o.z = x2[r] + y2[2] - 2.f * acc[r][2];
        o.w = x2[r] + y2[3] - 2.f * acc[r][3];
        *(float4*)&Sb[(i0 + ty * 4 + r) * 512 + j0 + tx * 4] = o;
    }
}

// ================= reskew: M[512][512] -> F4[u][t][q], base-2 scaled ============
// F[u][t][q] = LOG2E * M[2(u-t) + (q>>1)][2t + (q&1)]  if 0 <= u-t < 256, else 0
__global__ void __launch_bounds__(256) reskew_kernel(const float* __restrict__ go,
                                                     const float* __restrict__ ge) {
    int m = blockIdx.y;                 // 0..3 = S batches, 4 = go, 5 = ge
    int ut = blockIdx.x >> 3;           // 16 u-tiles of 32
    int jt = blockIdx.x & 7;            // 8 t-tiles of 32
    const float* src = (m < 4) ? (g_S + m * 262144) : ((m == 4) ? go : ge);
    float* dst = (m < 4) ? (float*)(g_Sf4 + m * (FU * 256)) :
                 ((m == 4) ? (float*)g_gof4 : (float*)g_gef4);
    int u0 = ut * 32, t0 = jt * 32;
    int rbase = 2 * (u0 - t0) - 62;     // 126 src rows
    int cbase = 2 * t0;                 // 64 src cols
    __shared__ float sm[126 * 65];
    int tid = threadIdx.x;
    #pragma unroll
    for (int l = 0; l < 32; l++) {
        int e = tid + l * 256;
        if (e < 126 * 64) {
            int rr = e >> 6, cc = e & 63;
            int gr = rbase + rr;
            sm[rr * 65 + cc] = (gr >= 0 && gr < 512) ?
                LOG2E * src[gr * 512 + cbase + cc] : 0.f;
        }
    }
    __syncthreads();
    #pragma unroll
    for (int l = 0; l < 16; l++) {
        int e = tid + l * 256;           // 4096 dst elements
        int q = e & 3, tr = (e >> 2) & 31, ur = e >> 7;
        int u = u0 + ur, t = t0 + tr;
        int dq = u - t;
        float v = 0.f;
        if (dq >= 0 && dq < 256) {
            int rr = 2 * (ur - tr) + (q >> 1) + 62;
            v = sm[rr * 65 + 2 * tr + (q & 1)];
        }
        dst[(u * 256 + t) * 4 + q] = v;
    }
}

// ================= wavefront soft-SW; 1 CTA/batch, 2x2 cells/thread/step ========
__global__ __launch_bounds__(SWT, 1) void sw_kernel() {
    const int b = blockIdx.x;
    const int t = threadIdx.x, lane = t & 31, warp = t >> 5;
    const float4* S4  = g_Sf4 + b * (FU * 256);
    const float4* go4 = g_gof4;
    const float4* ge4 = g_gef4;
    float4* Df4 = g_Df4 + b * (FU * 256);

    __shared__ float sh[2][8][8];   // [parity][warp][Dlo,Ixlo,glo,Dhi,Ixhi,ghi,pad,pad]
    if (t < 128) {
        int q = t & 7;
        ((float*)sh)[t] = (q == 2 || q == 5) ? 0.f : NEGV;
    }

    // carried state (previous superstep's hi row of own columns)
    float hA = NEGV, IyA = NEGV, gA = 0.f;
    float hB = NEGV, IyB = NEGV;
    // values passed rightward (own B column, lo & hi rows of last superstep)
    float BDlo = NEGV, BIlo = NEGV, Bglo = 0.f;
    float BDhi = NEGV, BIhi = NEGV, Bghi = 0.f;
    float gstale = 0.f;             // neighbor g at row (ra-1)

    float4 sP = S4[t], goP = go4[t], geP = ge4[t];
    __syncthreads();

    for (int u = 0; u < STEPS; u++) {
        float4 sC = sP, goC = goP, geC = geP;
        {
            int idx = (u + 1) * 256 + t;
            sP = S4[idx]; goP = go4[idx]; geP = ge4[idx];
        }
        // neighbor exchange (neighbor's previous-superstep B-column rows)
        float nDlo = __shfl_up_sync(0xffffffffu, BDlo, 1);
        float nIlo = __shfl_up_sync(0xffffffffu, BIlo, 1);
        float nglo = __shfl_up_sync(0xffffffffu, Bglo, 1);
        float nDhi = __shfl_up_sync(0xffffffffu, BDhi, 1);
        float nIhi = __shfl_up_sync(0xffffffffu, BIhi, 1);
        float nghi = __shfl_up_sync(0xffffffffu, Bghi, 1);
        {   // lane0 fixup: broadcast LDS + select (no divergent branch)
            int p = (u + 1) & 1;
            int wsel = (warp > 0) ? warp - 1 : 0;
            float sD0 = sh[p][wsel][0], sI0 = sh[p][wsel][1], sg0 = sh[p][wsel][2];
            float sD1 = sh[p][wsel][3], sI1 = sh[p][wsel][4], sg1 = sh[p][wsel][5];
            bool l0 = (lane == 0);
            bool w0 = (warp == 0);
            if (l0) {
                nDlo = w0 ? NEGV : sD0;  nIlo = w0 ? NEGV : sI0;  nglo = w0 ? 0.f : sg0;
                nDhi = w0 ? NEGV : sD1;  nIhi = w0 ? NEGV : sI1;  nghi = w0 ? 0.f : sg1;
            }
        }

        bool act = (u >= t) && (u - t < 256);
        if (act) {
            // rows ra = 2(u-t), rb = ra+1; cols ja = 2t, jb = 2t+1
            float ix1 = lse2b(nDlo - goC.x, nIlo - geC.x);
            float iy1 = lse2b(hA - goC.x, IyA - geC.x);
            float d1  = sC.x + gstale;
            float h1  = lse2b(d1, ix1);
            float g1  = lse3b(h1, iy1);

            float ix2 = lse2b(d1 - goC.y, ix1 - geC.y);
            float iy2 = lse2b(hB - goC.y, IyB - geC.y);
            float d2  = sC.y + gA;
            float h2  = lse2b(d2, ix2);
            float g2  = lse3b(h2, iy2);

            float ix3 = lse2b(nDhi - goC.z, nIhi - geC.z);
            float iy3 = lse2b(h1 - goC.z, iy1 - geC.z);
            float d3  = sC.z + nglo;
            float h3  = lse2b(d3, ix3);
            float g3  = lse3b(h3, iy3);

            float ix4 = lse2b(d3 - goC.w, ix3 - geC.w);
            float iy4 = lse2b(h2 - goC.w, iy2 - geC.w);
            float d4  = sC.w + g1;
            float h4  = lse2b(d4, ix4);
            float g4  = lse3b(h4, iy4);

            Df4[u * 256 + t] = make_float4(d1, d2, d3, d4);

            hA = h3; IyA = iy3; gA = g3;
            hB = h4; IyB = iy4;
            BDlo = d2; BIlo = ix2; Bglo = g2;
            BDhi = d4; BIhi = ix4; Bghi = g4;
        }
        gstale = nghi;
        if (lane == 31) {
            sh[u & 1][warp][0] = BDlo; sh[u & 1][warp][1] = BIlo; sh[u & 1][warp][2] = Bglo;
            sh[u & 1][warp][3] = BDhi; sh[u & 1][warp][4] = BIhi; sh[u & 1][warp][5] = Bghi;
        }
        __syncthreads();
    }
}

// ================= deskew + fused LSE: probas + per-block LSE partials ==========
// probas[r][j] = LN2 * Df4[(j>>1) + (r>>1)][j>>1].q ; every output element is a
// valid D value, so the block LSE accumulates over exactly its 2048 elements.
__global__ void __launch_bounds__(256) deskew_kernel(float* __restrict__ out) {
    int b = blockIdx.y;
    const float* Df = (const float*)(g_Df4 + b * (FU * 256));
    float* ob = out + 1 + b * 262144;
    int e0 = blockIdx.x * 256 + threadIdx.x;     // 128 blocks
    float m = NEGV, s = 0.f;
    #pragma unroll
    for (int l = 0; l < 8; l++) {
        int e = e0 + l * 32768;
        int r = e >> 9, j = e & 511;
        int tc = j >> 1;
        int u = tc + (r >> 1);
        int q = ((r & 1) << 1) | (j & 1);
        float v = Df[(u * 256 + tc) * 4 + q];    // base-2 domain
        ob[e] = LN2 * v;
        float nm = fmaxf(m, v);
        s = s * ex2a(m - nm) + ex2a(v - nm);
        m = nm;
    }
    __shared__ float sm[256], ss[256];
    int tid = threadIdx.x;
    sm[tid] = m; ss[tid] = s;
    __syncthreads();
    for (int o = 128; o > 0; o >>= 1) {
        if (tid < o) {
            float m2 = sm[tid + o], s2 = ss[tid + o];
            float nm = fmaxf(sm[tid], m2);
            ss[tid] = ss[tid] * ex2a(sm[tid] - nm) + s2 * ex2a(m2 - nm);
            sm[tid] = nm;
        }
        __syncthreads();
    }
    if (tid == 0) { g_pm[b * 128 + blockIdx.x] = sm[0]; g_ps[b * 128 + blockIdx.x] = ss[0]; }
}

__global__ void lse_final(float* __restrict__ out) {
    int t = threadIdx.x;              // 256
    int b = t >> 6, r = t & 63;
    float m = g_pm[b * 128 + r], s = g_ps[b * 128 + r];
    {
        float m2 = g_pm[b * 128 + 64 + r], s2 = g_ps[b * 128 + 64 + r];
        float nm = fmaxf(m, m2);
        s = s * ex2a(m - nm) + s2 * ex2a(m2 - nm);
        m = nm;
    }
    __shared__ float sm[256], ss[256], vv[4];
    sm[t] = m; ss[t] = s;
    __syncthreads();
    for (int o = 32; o > 0; o >>= 1) {
        if (r < o) {
            float m2 = sm[t + o], s2 = ss[t + o];
            float nm = fmaxf(sm[t], m2);
            ss[t] = ss[t] * ex2a(sm[t] - nm) + s2 * ex2a(m2 - nm);
            sm[t] = nm;
        }
        __syncthreads();
    }
    if (r == 0) vv[b] = LN2 * (sm[t] + lg2a(ss[t]));
    __syncthreads();
    if (t == 0) out[0] = 0.25f * (vv[0] + vv[1] + vv[2] + vv[3]);
}

// ================= launcher =================
extern "C" void kernel_launch(void* const* d_in, const int* in_sizes, int n_in,
                              void* d_out, int out_size) {
    const float* x  = (const float*)d_in[0];
    const float* y  = (const float*)d_in[1];
    const float* go = (const float*)d_in[2];
    const float* ge = (const float*)d_in[3];
    float* out = (float*)d_out;

    norm_kernel<<<32, 256>>>(x, y);
    dist_kernel<<<dim3(8, 8, 4), 256>>>(x, y);
    reskew_kernel<<<dim3(128, 6), 256>>>(go, ge);
    sw_kernel<<<4, SWT>>>();
    deskew_kernel<<<dim3(128, 4), 256>>>(out);
    lse_final<<<1, 256>>>(out);
}